// round 1
// baseline (speedup 1.0000x reference)
#include <cuda_runtime.h>

#define N       4096
#define THREADS 256
#define SMEM_WORDS (4096 + 128)   // +1 word per 32 for bank-conflict-free padding

__global__ __launch_bounds__(THREADS)
void fwht_kernel(const float* __restrict__ x,
                 const float* __restrict__ s,
                 float* __restrict__ out)
{
    __shared__ float sm[SMEM_WORDS];

    const int row  = blockIdx.x;
    const int t    = threadIdx.x;
    const int lane = t & 31;
    const int w    = t >> 5;

    const float* xr = x + (size_t)row * N + t * 16;
    const float* sr = s + t * 16;

    float v[16];

    // ---- load 16 contiguous elements, apply sign ----
    #pragma unroll
    for (int j = 0; j < 4; j++) {
        float4 xv = reinterpret_cast<const float4*>(xr)[j];
        float4 sv = reinterpret_cast<const float4*>(sr)[j];
        v[4*j+0] = xv.x * sv.x;
        v[4*j+1] = xv.y * sv.y;
        v[4*j+2] = xv.z * sv.z;
        v[4*j+3] = xv.w * sv.w;
    }

    // ---- FWHT over register bits [3:0] (4 levels) ----
    #pragma unroll
    for (int m = 1; m < 16; m <<= 1) {
        #pragma unroll
        for (int r = 0; r < 16; r++) {
            if ((r & m) == 0) {
                float a = v[r], b = v[r | m];
                v[r]     = a + b;
                v[r | m] = a - b;
            }
        }
    }

    // ---- FWHT over lane bits [8:4] (5 shuffle levels) ----
    #pragma unroll
    for (int m = 1; m < 32; m <<= 1) {
        const float sgn = (lane & m) ? -1.0f : 1.0f;
        #pragma unroll
        for (int r = 0; r < 16; r++) {
            float other = __shfl_xor_sync(0xffffffffu, v[r], m);
            // (lane&m)==0: v+other ; else: other - v   ==  other + sgn*v
            v[r] = __fmaf_rn(sgn, v[r], other);
        }
    }

    // ---- transpose via shared memory so register bits cover bits [11:9] ----
    // write at logical index i = t*16 + r   (padded addressing: conflict-free)
    #pragma unroll
    for (int r = 0; r < 16; r++) {
        int i = t * 16 + r;
        sm[i + (i >> 5)] = v[r];
    }
    __syncthreads();

    // read: reg rp -> logical index i' with bits[11:9]=rp[2:0], bit[8]=rp[3],
    //       bits[7:5]=w, bits[4:0]=lane   (lane-contiguous -> conflict-free)
    float u[16];
    #pragma unroll
    for (int rp = 0; rp < 16; rp++) {
        int i = ((rp & 7) << 9) | ((rp >> 3) << 8) | (w << 5) | lane;
        u[rp] = sm[i + (i >> 5)];
    }

    // ---- FWHT over remaining bits [11:9] = rp bits [2:0] (3 levels) ----
    #pragma unroll
    for (int m = 1; m < 8; m <<= 1) {
        #pragma unroll
        for (int rp = 0; rp < 16; rp++) {
            if ((rp & m) == 0) {
                float a = u[rp], b = u[rp | m];
                u[rp]     = a + b;
                u[rp | m] = a - b;
            }
        }
    }

    // ---- scaled store; for fixed rp the 32 lanes hit 32 contiguous floats ----
    const float scale = 0.015625f;  // 1/sqrt(4096)
    float* orow = out + (size_t)row * N;
    #pragma unroll
    for (int rp = 0; rp < 16; rp++) {
        int i = ((rp & 7) << 9) | ((rp >> 3) << 8) | (w << 5) | lane;
        orow[i] = u[rp] * scale;
    }
}

extern "C" void kernel_launch(void* const* d_in, const int* in_sizes, int n_in,
                              void* d_out, int out_size)
{
    const float* x = (const float*)d_in[0];
    const float* s = (const float*)d_in[1];
    float* out     = (float*)d_out;

    const int rows = in_sizes[0] / N;   // 16384
    fwht_kernel<<<rows, THREADS>>>(x, s, out);
}